// round 10
// baseline (speedup 1.0000x reference)
#include <cuda_runtime.h>
#include <math.h>
#include <stdint.h>

#define BB 2
#define NSEQ 2048
#define DD 1024
#define NH 16
#define HS 64
#define MM (BB*NSEQ)   // 4096 rows

// ---------------- scratch (allocation-free, __device__ globals) ----------------
__device__ float g_xn [MM*DD];
__device__ float g_qkv[MM*3*DD];
__device__ float g_oh [MM*DD];
__device__ float g_x1 [MM*DD];
__device__ float g_xn2[MM*DD];
__device__ float g_y  [MM*2*DD];
// transposed + tf32-rounded weights [N][K]
__device__ float g_wqkv[DD*3*DD];
__device__ float g_wout[DD*DD];
__device__ float g_w1  [DD*2*DD];
__device__ float g_w2  [2*DD*DD];

__device__ __forceinline__ float gelu_tanh(float x){
    float u = 0.7978845608028654f * (x + 0.044715f*x*x*x);
    float t = 1.0f - 2.0f/(__expf(2.0f*u)+1.0f);
    return 0.5f*x*(1.0f+t);
}

__device__ __forceinline__ float tf32r(float x){
    uint32_t r;
    asm volatile("cvt.rna.tf32.f32 %0, %1;" : "=r"(r) : "f"(x));
    return __uint_as_float(r);
}

__device__ __forceinline__ void cp_async16(void* smem, const void* gmem){
    unsigned s = (unsigned)__cvta_generic_to_shared(smem);
    asm volatile("cp.async.cg.shared.global [%0], [%1], 16;" :: "r"(s), "l"(gmem));
}
__device__ __forceinline__ void cp_commit(){ asm volatile("cp.async.commit_group;"); }
template<int N> __device__ __forceinline__ void cp_wait(){ asm volatile("cp.async.wait_group %0;" :: "n"(N)); }

__device__ __forceinline__ void mma_tf32(float c[4], uint32_t a0, uint32_t a1,
                                         uint32_t a2, uint32_t a3,
                                         uint32_t b0, uint32_t b1){
    asm volatile(
        "mma.sync.aligned.m16n8k8.row.col.f32.tf32.tf32.f32 "
        "{%0,%1,%2,%3},{%4,%5,%6,%7},{%8,%9},{%0,%1,%2,%3};"
        : "+f"(c[0]), "+f"(c[1]), "+f"(c[2]), "+f"(c[3])
        : "r"(a0), "r"(a1), "r"(a2), "r"(a3), "r"(b0), "r"(b1));
}

__device__ __forceinline__ uint32_t s2u(const void* p){
    return (uint32_t)__cvta_generic_to_shared(p);
}
#define LDSM_X4(r0,r1,r2,r3, addr) \
    asm volatile("ldmatrix.sync.aligned.m8n8.x4.shared.b16 {%0,%1,%2,%3}, [%4];" \
        : "=r"(r0), "=r"(r1), "=r"(r2), "=r"(r3) : "r"(addr))

// ---------------- weight prep: W[K][N] fp32 -> Wt[N][K], tf32-rounded ----------------
__global__ __launch_bounds__(256) void wtrans_kernel(const float* __restrict__ W,
                                                     float* __restrict__ Wt,
                                                     int K, int N)
{
    __shared__ float tile[32][33];
    const int k0 = blockIdx.y*32, n0 = blockIdx.x*32;
    const int tx = threadIdx.x & 31, ty = threadIdx.x >> 5;
    for (int r = ty; r < 32; r += 8)
        tile[r][tx] = W[(size_t)(k0+r)*N + n0 + tx];
    __syncthreads();
    for (int r = ty; r < 32; r += 8)
        Wt[(size_t)(n0+r)*K + k0 + tx] = tf32r(tile[tx][r]);
}

// ---------------- LayerNorm: one block per row, output tf32-rounded ----------------
__global__ __launch_bounds__(256) void ln_kernel(const float* __restrict__ x,
        const float* __restrict__ sc, const float* __restrict__ bi,
        float* __restrict__ out)
{
    const int row = blockIdx.x;
    const int t = threadIdx.x;
    const float4 v = ((const float4*)(x + (size_t)row*DD))[t];
    float s  = v.x+v.y+v.z+v.w;
    float sq = v.x*v.x+v.y*v.y+v.z*v.z+v.w*v.w;
    #pragma unroll
    for (int o=16;o>0;o>>=1){
        s  += __shfl_xor_sync(0xffffffffu,s ,o);
        sq += __shfl_xor_sync(0xffffffffu,sq,o);
    }
    __shared__ float ss[8], sqs[8];
    const int warp=t>>5, lane=t&31;
    if (lane==0){ ss[warp]=s; sqs[warp]=sq; }
    __syncthreads();
    if (t==0){
        float a=0.f,b=0.f;
        #pragma unroll
        for(int i=0;i<8;i++){a+=ss[i]; b+=sqs[i];}
        ss[0]=a; sqs[0]=b;
    }
    __syncthreads();
    const float mean = ss[0]*(1.0f/DD);
    const float var  = sqs[0]*(1.0f/DD) - mean*mean;
    const float inv  = rsqrtf(var + 1e-6f);
    const float4 sc4 = ((const float4*)sc)[t];
    const float4 bi4 = ((const float4*)bi)[t];
    float4 o4;
    o4.x = tf32r((v.x-mean)*inv*sc4.x + bi4.x);
    o4.y = tf32r((v.y-mean)*inv*sc4.y + bi4.y);
    o4.z = tf32r((v.z-mean)*inv*sc4.z + bi4.z);
    o4.w = tf32r((v.w-mean)*inv*sc4.w + bi4.w);
    ((float4*)(out + (size_t)row*DD))[t] = o4;
}

// ---------------- TF32 GEMM 128x128x16, LDSM operand feed, 3-stage pipeline ----------------
// A [M][K] row-major (activations, pre-rounded). B = Wt [N][K] (transposed, pre-rounded).
// smem: As[m][k], Bs[n][k], both stride 20 (8 rows of a LDSM tile hit 8 distinct
// 16B groups: 80B*r mod 128 = {0,80,32,112,64,16,96,48}).
#define TSTRIDE 20
#define NSTG 3
template<int EPI>
__global__ __launch_bounds__(256) void tgemm_kernel(
    const float* __restrict__ A, const float* __restrict__ B,
    float* __restrict__ C, int M, int N, int K,
    const float* __restrict__ bias, const float* __restrict__ res)
{
    extern __shared__ float smg[];
    float (*As)[128][TSTRIDE] = (float(*)[128][TSTRIDE])smg;
    float (*Bs)[128][TSTRIDE] = (float(*)[128][TSTRIDE])(smg + NSTG*128*TSTRIDE);

    const int tid  = threadIdx.x;
    const int lane = tid & 31;
    const int warp = tid >> 5;
    const int wm = warp >> 1;        // 0..3
    const int wn = warp & 1;         // 0..1
    const int mB = wm*32;
    const int nB = wn*64;
    const int bm = blockIdx.y*128;
    const int bn = blockIdx.x*128;

    // loaders (identical pattern for A and B): 16B chunks along K
    const int lr  = tid >> 2;        // 0..63
    const int lc4 = (tid & 3) << 2;  // 0,4,8,12

    const float* Ag0 = A + (size_t)(bm + lr     )*K + lc4;
    const float* Ag1 = A + (size_t)(bm + lr + 64)*K + lc4;
    const float* Bg0 = B + (size_t)(bn + lr     )*K + lc4;
    const float* Bg1 = B + (size_t)(bn + lr + 64)*K + lc4;

    const int nk = K >> 4;

    // prologue: stages 0 and 1
    #pragma unroll
    for (int p = 0; p < 2; p++){
        const int ko = p << 4;
        cp_async16(&As[p][lr     ][lc4], Ag0 + ko);
        cp_async16(&As[p][lr + 64][lc4], Ag1 + ko);
        cp_async16(&Bs[p][lr     ][lc4], Bg0 + ko);
        cp_async16(&Bs[p][lr + 64][lc4], Bg1 + ko);
        cp_commit();
    }

    float acc[2][8][4] = {};

    // LDSM per-lane addressing
    // A x4 (frag i): lanes 0-7 rows m..m+7 k-lo, 8-15 m+8..15 k-lo, 16-23 m..m+7 k-hi, 24-31 m+8..15 k-hi
    const int aRow = mB + (lane & 7) + ((lane >> 3) & 1)*8;
    const int aCol = (lane >> 4)*4;
    // B x4 (frag pair p -> frags 2p,2p+1): lanes 0-7 n..n+7 k-lo, 8-15 n..n+7 k-hi,
    //                                      16-23 n+8..15 k-lo, 24-31 n+8..15 k-hi
    const int bRow = nB + ((lane >> 4) & 1)*8 + (lane & 7);
    const int bCol = ((lane >> 3) & 1)*4;

    int cur = 0;
    for (int kt = 0; kt < nk; kt++){
        cp_wait<1>();
        __syncthreads();

        if (kt + 2 < nk){
            int nxt = cur + 2;
            if (nxt >= NSTG) nxt -= NSTG;
            const int ko = (kt+2) << 4;
            cp_async16(&As[nxt][lr     ][lc4], Ag0 + ko);
            cp_async16(&As[nxt][lr + 64][lc4], Ag1 + ko);
            cp_async16(&Bs[nxt][lr     ][lc4], Bg0 + ko);
            cp_async16(&Bs[nxt][lr + 64][lc4], Bg1 + ko);
            cp_commit();
        }

        #pragma unroll
        for (int kk = 0; kk < 2; kk++){
            const int kc8 = kk*8;
            uint32_t af[2][4], bf[8][2];
            #pragma unroll
            for (int i = 0; i < 2; i++){
                const uint32_t addr = s2u(&As[cur][aRow + i*16][kc8 + aCol]);
                LDSM_X4(af[i][0], af[i][1], af[i][2], af[i][3], addr);
            }
            #pragma unroll
            for (int p = 0; p < 4; p++){
                const uint32_t addr = s2u(&Bs[cur][bRow + p*16][kc8 + bCol]);
                LDSM_X4(bf[2*p][0], bf[2*p][1], bf[2*p+1][0], bf[2*p+1][1], addr);
            }
            #pragma unroll
            for (int i = 0; i < 2; i++)
                #pragma unroll
                for (int j = 0; j < 8; j++)
                    mma_tf32(acc[i][j], af[i][0], af[i][1], af[i][2], af[i][3],
                             bf[j][0], bf[j][1]);
        }
        cur = (cur + 1 == NSTG) ? 0 : cur + 1;
    }

    const int frow = lane >> 2;
    const int fcol = lane & 3;
    #pragma unroll
    for (int i = 0; i < 2; i++){
        const int row = bm + mB + i*16 + frow;
        #pragma unroll
        for (int j = 0; j < 8; j++){
            const int col = bn + nB + j*8 + fcol*2;
            float v0 = acc[i][j][0], v1 = acc[i][j][1];
            float v2 = acc[i][j][2], v3 = acc[i][j][3];
            const size_t o0 = (size_t)row*N + col;
            const size_t o1 = (size_t)(row+8)*N + col;
            if (EPI == 0){
                v0 = tf32r(v0); v1 = tf32r(v1); v2 = tf32r(v2); v3 = tf32r(v3);
            } else if (EPI == 1){
                const float b0 = bias[col], b1 = bias[col+1];
                v0 += b0 + res[o0];   v1 += b1 + res[o0+1];
                v2 += b0 + res[o1];   v3 += b1 + res[o1+1];
            } else if (EPI == 2){
                const float b0 = bias[col], b1 = bias[col+1];
                v0 = tf32r(gelu_tanh(v0 + b0)); v1 = tf32r(gelu_tanh(v1 + b1));
                v2 = tf32r(gelu_tanh(v2 + b0)); v3 = tf32r(gelu_tanh(v3 + b1));
            }
            *(float2*)(C + o0) = make_float2(v0, v1);
            *(float2*)(C + o1) = make_float2(v2, v3);
        }
    }
}

// ---------------- Causal flash attention on tensor cores (tf32) ----------------
#define ATS 68
__global__ __launch_bounds__(128, 3) void attn_tc_kernel(const float* __restrict__ qkv,
                                                         float* __restrict__ oh)
{
    extern __shared__ float sm[];
    float* Qs = sm;
    float* KP = sm + 64*ATS;
    float* Vt = sm + 2*64*ATS;

    const int qt = gridDim.x - 1 - blockIdx.x;
    const int bh = blockIdx.y;
    const int b = bh >> 4;
    const int h = bh & 15;
    const int tid = threadIdx.x;
    const int lane = tid & 31;
    const int warp = tid >> 5;
    const int mB = warp * 16;
    const int g = lane >> 2;
    const int c = lane & 3;
    const size_t base = (size_t)b * NSEQ * (3*DD);
    const int hoff = h * HS;

    for (int i = tid; i < 64*16; i += 128){
        const int row = i >> 4, d4 = (i & 15) << 2;
        const float4 q4 = *(const float4*)(qkv + base + (size_t)(qt*64+row)*(3*DD) + hoff + d4);
        *(float4*)&Qs[row*ATS + d4] = q4;
    }
    __syncthreads();

    uint32_t qa[8][4];
    #pragma unroll
    for (int kk = 0; kk < 8; kk++){
        qa[kk][0] = __float_as_uint(Qs[(mB+g  )*ATS + kk*8 + c    ]);
        qa[kk][1] = __float_as_uint(Qs[(mB+g+8)*ATS + kk*8 + c    ]);
        qa[kk][2] = __float_as_uint(Qs[(mB+g  )*ATS + kk*8 + c + 4]);
        qa[kk][3] = __float_as_uint(Qs[(mB+g+8)*ATS + kk*8 + c + 4]);
    }

    float o[8][4] = {};
    float m0=-1e30f, m1=-1e30f, l0=0.f, l1=0.f;

    const int r0g = qt*64 + mB + g;
    const int r1g = r0g + 8;

    for (int jt = 0; jt <= qt; jt++){
        __syncthreads();
        for (int i = tid; i < 64*16; i += 128){
            const int row = i >> 4, d4 = (i & 15) << 2;
            const size_t roff = base + (size_t)(jt*64+row)*(3*DD) + hoff + d4;
            const float4 k4 = *(const float4*)(qkv + roff + DD);
            *(float4*)&KP[row*ATS + d4] = k4;
            const float4 v4 = *(const float4*)(qkv + roff + 2*DD);
            Vt[(d4+0)*ATS+row]=v4.x; Vt[(d4+1)*ATS+row]=v4.y;
            Vt[(d4+2)*ATS+row]=v4.z; Vt[(d4+3)*ATS+row]=v4.w;
        }
        __syncthreads();

        float s[8][4] = {};
        #pragma unroll
        for (int kk = 0; kk < 8; kk++){
            #pragma unroll
            for (int j = 0; j < 8; j++){
                const uint32_t b0 = __float_as_uint(KP[(j*8+g)*ATS + kk*8 + c    ]);
                const uint32_t b1 = __float_as_uint(KP[(j*8+g)*ATS + kk*8 + c + 4]);
                mma_tf32(s[j], qa[kk][0], qa[kk][1], qa[kk][2], qa[kk][3], b0, b1);
            }
        }
        __syncthreads();

        float rm0 = -1e30f, rm1 = -1e30f;
        #pragma unroll
        for (int j = 0; j < 8; j++){
            const int col = jt*64 + j*8 + 2*c;
            #pragma unroll
            for (int t2 = 0; t2 < 2; t2++){
                float v0 = s[j][t2]*0.125f;
                float v1 = s[j][2+t2]*0.125f;
                if (jt == qt){
                    if (col+t2 > r0g) v0 = -1e30f;
                    if (col+t2 > r1g) v1 = -1e30f;
                }
                s[j][t2] = v0;  s[j][2+t2] = v1;
                rm0 = fmaxf(rm0, v0); rm1 = fmaxf(rm1, v1);
            }
        }
        #pragma unroll
        for (int off = 1; off <= 2; off <<= 1){
            rm0 = fmaxf(rm0, __shfl_xor_sync(0xffffffffu, rm0, off));
            rm1 = fmaxf(rm1, __shfl_xor_sync(0xffffffffu, rm1, off));
        }
        const float mn0 = fmaxf(m0, rm0), mn1 = fmaxf(m1, rm1);
        const float alpha0 = __expf(m0 - mn0), alpha1 = __expf(m1 - mn1);
        m0 = mn0; m1 = mn1;

        float rs0 = 0.f, rs1 = 0.f;
        #pragma unroll
        for (int j = 0; j < 8; j++){
            float p0 = __expf(s[j][0] - mn0);
            float p1 = __expf(s[j][1] - mn0);
            float p2 = __expf(s[j][2] - mn1);
            float p3 = __expf(s[j][3] - mn1);
            rs0 += p0 + p1;  rs1 += p2 + p3;
            *(float2*)&KP[(mB+g  )*ATS + j*8 + 2*c] = make_float2(tf32r(p0), tf32r(p1));
            *(float2*)&KP[(mB+g+8)*ATS + j*8 + 2*c] = make_float2(tf32r(p2), tf32r(p3));
        }
        #pragma unroll
        for (int off = 1; off <= 2; off <<= 1){
            rs0 += __shfl_xor_sync(0xffffffffu, rs0, off);
            rs1 += __shfl_xor_sync(0xffffffffu, rs1, off);
        }
        l0 = l0*alpha0 + rs0;
        l1 = l1*alpha1 + rs1;

        #pragma unroll
        for (int j = 0; j < 8; j++){
            o[j][0] *= alpha0; o[j][1] *= alpha0;
            o[j][2] *= alpha1; o[j][3] *= alpha1;
        }
        __syncwarp();

        #pragma unroll
        for (int kk = 0; kk < 8; kk++){
            const uint32_t a0 = __float_as_uint(KP[(mB+g  )*ATS + kk*8 + c    ]);
            const uint32_t a1 = __float_as_uint(KP[(mB+g+8)*ATS + kk*8 + c    ]);
            const uint32_t a2 = __float_as_uint(KP[(mB+g  )*ATS + kk*8 + c + 4]);
            const uint32_t a3 = __float_as_uint(KP[(mB+g+8)*ATS + kk*8 + c + 4]);
            #pragma unroll
            for (int j = 0; j < 8; j++){
                const uint32_t b0 = __float_as_uint(Vt[(j*8+g)*ATS + kk*8 + c    ]);
                const uint32_t b1 = __float_as_uint(Vt[(j*8+g)*ATS + kk*8 + c + 4]);
                mma_tf32(o[j], a0, a1, a2, a3, b0, b1);
            }
        }
    }

    const float inv0 = 1.0f/l0, inv1 = 1.0f/l1;
    #pragma unroll
    for (int j = 0; j < 8; j++){
        const int col = hoff + j*8 + 2*c;
        float* p0 = oh + (size_t)(b*NSEQ + r0g)*DD + col;
        float* p1 = oh + (size_t)(b*NSEQ + r1g)*DD + col;
        *(float2*)p0 = make_float2(tf32r(o[j][0]*inv0), tf32r(o[j][1]*inv0));
        *(float2*)p1 = make_float2(tf32r(o[j][2]*inv1), tf32r(o[j][3]*inv1));
    }
}

// ---------------- launch ----------------
extern "C" void kernel_launch(void* const* d_in, const int* in_sizes, int n_in,
                              void* d_out, int out_size)
{
    const float* x    = (const float*)d_in[0];
    const float* ln1s = (const float*)d_in[1];
    const float* ln1b = (const float*)d_in[2];
    const float* wqkv = (const float*)d_in[3];
    const float* wout = (const float*)d_in[4];
    const float* bout = (const float*)d_in[5];
    const float* ln2s = (const float*)d_in[6];
    const float* ln2b = (const float*)d_in[7];
    const float* w1   = (const float*)d_in[8];
    const float* b1   = (const float*)d_in[9];
    const float* w2   = (const float*)d_in[10];
    const float* b2   = (const float*)d_in[11];
    float* out = (float*)d_out;

    float *p_xn,*p_qkv,*p_oh,*p_x1,*p_xn2,*p_y;
    float *p_wqkv,*p_wout,*p_w1,*p_w2;
    cudaGetSymbolAddress((void**)&p_xn , g_xn );
    cudaGetSymbolAddress((void**)&p_qkv, g_qkv);
    cudaGetSymbolAddress((void**)&p_oh , g_oh );
    cudaGetSymbolAddress((void**)&p_x1 , g_x1 );
    cudaGetSymbolAddress((void**)&p_xn2, g_xn2);
    cudaGetSymbolAddress((void**)&p_y  , g_y  );
    cudaGetSymbolAddress((void**)&p_wqkv, g_wqkv);
    cudaGetSymbolAddress((void**)&p_wout, g_wout);
    cudaGetSymbolAddress((void**)&p_w1  , g_w1  );
    cudaGetSymbolAddress((void**)&p_w2  , g_w2  );

    const int attn_smem = 3*64*ATS*sizeof(float);
    cudaFuncSetAttribute(attn_tc_kernel, cudaFuncAttributeMaxDynamicSharedMemorySize, attn_smem);
    const int gemm_smem = 2*NSTG*128*TSTRIDE*sizeof(float);   // 61440
    cudaFuncSetAttribute(tgemm_kernel<0>, cudaFuncAttributeMaxDynamicSharedMemorySize, gemm_smem);
    cudaFuncSetAttribute(tgemm_kernel<1>, cudaFuncAttributeMaxDynamicSharedMemorySize, gemm_smem);
    cudaFuncSetAttribute(tgemm_kernel<2>, cudaFuncAttributeMaxDynamicSharedMemorySize, gemm_smem);

    // weight prep: transpose [K][N] -> [N][K] + tf32 round
    wtrans_kernel<<<dim3(3*DD/32, DD/32),256>>>(wqkv, p_wqkv, DD, 3*DD);
    wtrans_kernel<<<dim3(DD/32,   DD/32),256>>>(wout, p_wout, DD, DD);
    wtrans_kernel<<<dim3(2*DD/32, DD/32),256>>>(w1,   p_w1,   DD, 2*DD);
    wtrans_kernel<<<dim3(DD/32, 2*DD/32),256>>>(w2,   p_w2,   2*DD, DD);

    ln_kernel<<<MM,256>>>(x, ln1s, ln1b, p_xn);
    tgemm_kernel<0><<<dim3(3*DD/128, MM/128),256,gemm_smem>>>(p_xn, p_wqkv, p_qkv, MM, 3*DD, DD, nullptr, nullptr);
    attn_tc_kernel<<<dim3(NSEQ/64, BB*NH),128,attn_smem>>>(p_qkv, p_oh);
    tgemm_kernel<1><<<dim3(DD/128, MM/128),256,gemm_smem>>>(p_oh, p_wout, p_x1, MM, DD, DD, bout, x);
    ln_kernel<<<MM,256>>>(p_x1, ln2s, ln2b, p_xn2);
    tgemm_kernel<2><<<dim3(2*DD/128, MM/128),256,gemm_smem>>>(p_xn2, p_w1, p_y, MM, 2*DD, DD, b1, nullptr);
    tgemm_kernel<1><<<dim3(DD/128, MM/128),256,gemm_smem>>>(p_y, p_w2, out, MM, DD, 2*DD, b2, p_x1);
}

// round 11
// speedup vs baseline: 1.8676x; 1.8676x over previous
#include <cuda_runtime.h>
#include <cuda_fp16.h>
#include <math.h>
#include <stdint.h>

#define BB 2
#define NSEQ 2048
#define DD 1024
#define NH 16
#define HS 64
#define MM (BB*NSEQ)   // 4096 rows

// ---------------- scratch (allocation-free, __device__ globals) ----------------
__device__ __align__(16) __half g_xn [(size_t)MM*DD];      // LN1 out fp16
__device__ float g_qkv[(size_t)MM*3*DD];                    // QKV fp32 (tf32-rounded)
__device__ __align__(16) __half g_oh [(size_t)MM*DD];      // attn out fp16
__device__ float g_x1 [(size_t)MM*DD];                      // residual fp32
__device__ __align__(16) __half g_xn2[(size_t)MM*DD];      // LN2 out fp16
__device__ __align__(16) __half g_y  [(size_t)MM*2*DD];    // MLP hidden fp16
// transposed fp16 weights [N][K]
__device__ __align__(16) __half g_wqkvh[(size_t)3*DD*DD];
__device__ __align__(16) __half g_wouth[(size_t)DD*DD];
__device__ __align__(16) __half g_w1h  [(size_t)2*DD*DD];
__device__ __align__(16) __half g_w2h  [(size_t)DD*2*DD];

__device__ __forceinline__ float gelu_tanh(float x){
    float u = 0.7978845608028654f * (x + 0.044715f*x*x*x);
    float t = 1.0f - 2.0f/(__expf(2.0f*u)+1.0f);
    return 0.5f*x*(1.0f+t);
}

__device__ __forceinline__ float tf32r(float x){
    uint32_t r;
    asm volatile("cvt.rna.tf32.f32 %0, %1;" : "=r"(r) : "f"(x));
    return __uint_as_float(r);
}

__device__ __forceinline__ void cp_async16(void* smem, const void* gmem){
    unsigned s = (unsigned)__cvta_generic_to_shared(smem);
    asm volatile("cp.async.cg.shared.global [%0], [%1], 16;" :: "r"(s), "l"(gmem));
}
__device__ __forceinline__ void cp_commit(){ asm volatile("cp.async.commit_group;"); }
template<int N> __device__ __forceinline__ void cp_wait(){ asm volatile("cp.async.wait_group %0;" :: "n"(N)); }

__device__ __forceinline__ void mma_tf32(float c[4], uint32_t a0, uint32_t a1,
                                         uint32_t a2, uint32_t a3,
                                         uint32_t b0, uint32_t b1){
    asm volatile(
        "mma.sync.aligned.m16n8k8.row.col.f32.tf32.tf32.f32 "
        "{%0,%1,%2,%3},{%4,%5,%6,%7},{%8,%9},{%0,%1,%2,%3};"
        : "+f"(c[0]), "+f"(c[1]), "+f"(c[2]), "+f"(c[3])
        : "r"(a0), "r"(a1), "r"(a2), "r"(a3), "r"(b0), "r"(b1));
}
__device__ __forceinline__ void mma_f16(float c[4], uint32_t a0, uint32_t a1,
                                        uint32_t a2, uint32_t a3,
                                        uint32_t b0, uint32_t b1){
    asm volatile(
        "mma.sync.aligned.m16n8k16.row.col.f32.f16.f16.f32 "
        "{%0,%1,%2,%3},{%4,%5,%6,%7},{%8,%9},{%0,%1,%2,%3};"
        : "+f"(c[0]), "+f"(c[1]), "+f"(c[2]), "+f"(c[3])
        : "r"(a0), "r"(a1), "r"(a2), "r"(a3), "r"(b0), "r"(b1));
}

// ---------------- weight prep: W[K][N] fp32 -> Wh[N][K] fp16 ----------------
__global__ __launch_bounds__(256) void wtrans_h_kernel(const float* __restrict__ W,
                                                       __half* __restrict__ Wh,
                                                       int K, int N)
{
    __shared__ float tile[32][33];
    const int k0 = blockIdx.y*32, n0 = blockIdx.x*32;
    const int tx = threadIdx.x & 31, ty = threadIdx.x >> 5;
    for (int r = ty; r < 32; r += 8)
        tile[r][tx] = W[(size_t)(k0+r)*N + n0 + tx];
    __syncthreads();
    for (int r = ty; r < 32; r += 8)
        Wh[(size_t)(n0+r)*K + k0 + tx] = __float2half_rn(tile[tx][r]);
}

// ---------------- LayerNorm -> fp16 ----------------
__global__ __launch_bounds__(256) void ln_kernel(const float* __restrict__ x,
        const float* __restrict__ sc, const float* __restrict__ bi,
        __half* __restrict__ out)
{
    const int row = blockIdx.x;
    const int t = threadIdx.x;
    const float4 v = ((const float4*)(x + (size_t)row*DD))[t];
    float s  = v.x+v.y+v.z+v.w;
    float sq = v.x*v.x+v.y*v.y+v.z*v.z+v.w*v.w;
    #pragma unroll
    for (int o=16;o>0;o>>=1){
        s  += __shfl_xor_sync(0xffffffffu,s ,o);
        sq += __shfl_xor_sync(0xffffffffu,sq,o);
    }
    __shared__ float ss[8], sqs[8];
    const int warp=t>>5, lane=t&31;
    if (lane==0){ ss[warp]=s; sqs[warp]=sq; }
    __syncthreads();
    if (t==0){
        float a=0.f,b=0.f;
        #pragma unroll
        for(int i=0;i<8;i++){a+=ss[i]; b+=sqs[i];}
        ss[0]=a; sqs[0]=b;
    }
    __syncthreads();
    const float mean = ss[0]*(1.0f/DD);
    const float var  = sqs[0]*(1.0f/DD) - mean*mean;
    const float inv  = rsqrtf(var + 1e-6f);
    const float4 sc4 = ((const float4*)sc)[t];
    const float4 bi4 = ((const float4*)bi)[t];
    __half2* p = (__half2*)(out + (size_t)row*DD + 4*t);
    p[0] = __floats2half2_rn((v.x-mean)*inv*sc4.x + bi4.x,
                             (v.y-mean)*inv*sc4.y + bi4.y);
    p[1] = __floats2half2_rn((v.z-mean)*inv*sc4.z + bi4.z,
                             (v.w-mean)*inv*sc4.w + bi4.w);
}

// ---------------- FP16 GEMM 128x128x32, m16n8k16, 3-stage pipeline ----------------
// A [M][K] fp16 row-major; B = Wh [N][K] fp16 (K contiguous). Scalar b32 operand loads.
// EPI: 0 = C=tf32r(acc) fp32 ; 1 = C=acc+bias+res fp32 ; 2 = Ch=fp16(gelu(acc+bias))
#define BK 32
#define HSTR 40     // fp16 units per row (80 B)
#define NSTG 3
template<int EPI>
__global__ __launch_bounds__(256) void hgemm_kernel(
    const __half* __restrict__ A, const __half* __restrict__ B,
    float* __restrict__ C, __half* __restrict__ Ch, int M, int N, int K,
    const float* __restrict__ bias, const float* __restrict__ res)
{
    extern __shared__ __half smh[];
    __half (*As)[128][HSTR] = (__half(*)[128][HSTR])smh;
    __half (*Bs)[128][HSTR] = (__half(*)[128][HSTR])(smh + (size_t)NSTG*128*HSTR);

    const int tid  = threadIdx.x;
    const int lane = tid & 31;
    const int warp = tid >> 5;
    const int wm = warp >> 1;        // 0..3
    const int wn = warp & 1;         // 0..1
    const int mB = wm*32;
    const int nB = wn*64;
    const int bm = blockIdx.y*128;
    const int bn = blockIdx.x*128;

    // loaders: 128 rows x 32 fp16 per tile; 2 x 16B per thread, chunks {c0, c0+2}
    const int lr = tid >> 1;         // 0..127
    const int c0 = (tid & 1);        // 0/1

    const __half* Ag = A + (size_t)(bm + lr)*K + c0*8;
    const __half* Bg = B + (size_t)(bn + lr)*K + c0*8;

    const int nk = K >> 5;

    #pragma unroll
    for (int p = 0; p < 2; p++){
        const int ko = p << 5;
        cp_async16(&As[p][lr][c0*8     ], Ag + ko);
        cp_async16(&As[p][lr][c0*8 + 16], Ag + ko + 16);
        cp_async16(&Bs[p][lr][c0*8     ], Bg + ko);
        cp_async16(&Bs[p][lr][c0*8 + 16], Bg + ko + 16);
        cp_commit();
    }

    float acc[2][8][4] = {};
    const int g = lane >> 2;   // 0..7
    const int c = lane & 3;    // 0..3

    int cur = 0;
    for (int kt = 0; kt < nk; kt++){
        cp_wait<1>();
        __syncthreads();

        if (kt + 2 < nk){
            int nxt = cur + 2;
            if (nxt >= NSTG) nxt -= NSTG;
            const int ko = (kt+2) << 5;
            cp_async16(&As[nxt][lr][c0*8     ], Ag + ko);
            cp_async16(&As[nxt][lr][c0*8 + 16], Ag + ko + 16);
            cp_async16(&Bs[nxt][lr][c0*8     ], Bg + ko);
            cp_async16(&Bs[nxt][lr][c0*8 + 16], Bg + ko + 16);
            cp_commit();
        }

        #pragma unroll
        for (int kk = 0; kk < 2; kk++){
            const int kb = kk*16 + 2*c;
            uint32_t af[2][4], bf[8][2];
            #pragma unroll
            for (int i = 0; i < 2; i++){
                const int r0 = mB + i*16 + g;
                af[i][0] = *(const uint32_t*)&As[cur][r0    ][kb    ];
                af[i][1] = *(const uint32_t*)&As[cur][r0 + 8][kb    ];
                af[i][2] = *(const uint32_t*)&As[cur][r0    ][kb + 8];
                af[i][3] = *(const uint32_t*)&As[cur][r0 + 8][kb + 8];
            }
            #pragma unroll
            for (int j = 0; j < 8; j++){
                const int n = nB + j*8 + g;
                bf[j][0] = *(const uint32_t*)&Bs[cur][n][kb    ];
                bf[j][1] = *(const uint32_t*)&Bs[cur][n][kb + 8];
            }
            #pragma unroll
            for (int i = 0; i < 2; i++)
                #pragma unroll
                for (int j = 0; j < 8; j++)
                    mma_f16(acc[i][j], af[i][0], af[i][1], af[i][2], af[i][3],
                            bf[j][0], bf[j][1]);
        }
        cur = (cur + 1 == NSTG) ? 0 : cur + 1;
    }

    #pragma unroll
    for (int i = 0; i < 2; i++){
        const int row = bm + mB + i*16 + g;
        #pragma unroll
        for (int j = 0; j < 8; j++){
            const int col = bn + nB + j*8 + c*2;
            float v0 = acc[i][j][0], v1 = acc[i][j][1];
            float v2 = acc[i][j][2], v3 = acc[i][j][3];
            const size_t o0 = (size_t)row*N + col;
            const size_t o1 = (size_t)(row+8)*N + col;
            if (EPI == 0){
                *(float2*)(C + o0) = make_float2(tf32r(v0), tf32r(v1));
                *(float2*)(C + o1) = make_float2(tf32r(v2), tf32r(v3));
            } else if (EPI == 1){
                const float b0 = bias[col], b1 = bias[col+1];
                *(float2*)(C + o0) = make_float2(v0 + b0 + res[o0], v1 + b1 + res[o0+1]);
                *(float2*)(C + o1) = make_float2(v2 + b0 + res[o1], v3 + b1 + res[o1+1]);
            } else {
                const float b0 = bias[col], b1 = bias[col+1];
                *(__half2*)(Ch + o0) = __floats2half2_rn(gelu_tanh(v0 + b0), gelu_tanh(v1 + b1));
                *(__half2*)(Ch + o1) = __floats2half2_rn(gelu_tanh(v2 + b0), gelu_tanh(v3 + b1));
            }
        }
    }
}

// ---------------- Causal flash attention on tensor cores (tf32), fp16 output ----------------
#define ATS 68
__global__ __launch_bounds__(128, 3) void attn_tc_kernel(const float* __restrict__ qkv,
                                                         __half* __restrict__ oh)
{
    extern __shared__ float sm[];
    float* Qs = sm;
    float* KP = sm + 64*ATS;
    float* Vt = sm + 2*64*ATS;

    const int qt = gridDim.x - 1 - blockIdx.x;
    const int bh = blockIdx.y;
    const int b = bh >> 4;
    const int h = bh & 15;
    const int tid = threadIdx.x;
    const int lane = tid & 31;
    const int warp = tid >> 5;
    const int mB = warp * 16;
    const int g = lane >> 2;
    const int c = lane & 3;
    const size_t base = (size_t)b * NSEQ * (3*DD);
    const int hoff = h * HS;

    for (int i = tid; i < 64*16; i += 128){
        const int row = i >> 4, d4 = (i & 15) << 2;
        const float4 q4 = *(const float4*)(qkv + base + (size_t)(qt*64+row)*(3*DD) + hoff + d4);
        *(float4*)&Qs[row*ATS + d4] = q4;
    }
    __syncthreads();

    uint32_t qa[8][4];
    #pragma unroll
    for (int kk = 0; kk < 8; kk++){
        qa[kk][0] = __float_as_uint(Qs[(mB+g  )*ATS + kk*8 + c    ]);
        qa[kk][1] = __float_as_uint(Qs[(mB+g+8)*ATS + kk*8 + c    ]);
        qa[kk][2] = __float_as_uint(Qs[(mB+g  )*ATS + kk*8 + c + 4]);
        qa[kk][3] = __float_as_uint(Qs[(mB+g+8)*ATS + kk*8 + c + 4]);
    }

    float o[8][4] = {};
    float m0=-1e30f, m1=-1e30f, l0=0.f, l1=0.f;

    const int r0g = qt*64 + mB + g;
    const int r1g = r0g + 8;

    for (int jt = 0; jt <= qt; jt++){
        __syncthreads();
        for (int i = tid; i < 64*16; i += 128){
            const int row = i >> 4, d4 = (i & 15) << 2;
            const size_t roff = base + (size_t)(jt*64+row)*(3*DD) + hoff + d4;
            const float4 k4 = *(const float4*)(qkv + roff + DD);
            *(float4*)&KP[row*ATS + d4] = k4;
            const float4 v4 = *(const float4*)(qkv + roff + 2*DD);
            Vt[(d4+0)*ATS+row]=v4.x; Vt[(d4+1)*ATS+row]=v4.y;
            Vt[(d4+2)*ATS+row]=v4.z; Vt[(d4+3)*ATS+row]=v4.w;
        }
        __syncthreads();

        float s[8][4] = {};
        #pragma unroll
        for (int kk = 0; kk < 8; kk++){
            #pragma unroll
            for (int j = 0; j < 8; j++){
                const uint32_t b0 = __float_as_uint(KP[(j*8+g)*ATS + kk*8 + c    ]);
                const uint32_t b1 = __float_as_uint(KP[(j*8+g)*ATS + kk*8 + c + 4]);
                mma_tf32(s[j], qa[kk][0], qa[kk][1], qa[kk][2], qa[kk][3], b0, b1);
            }
        }
        __syncthreads();

        float rm0 = -1e30f, rm1 = -1e30f;
        #pragma unroll
        for (int j = 0; j < 8; j++){
            const int col = jt*64 + j*8 + 2*c;
            #pragma unroll
            for (int t2 = 0; t2 < 2; t2++){
                float v0 = s[j][t2]*0.125f;
                float v1 = s[j][2+t2]*0.125f;
                if (jt == qt){
                    if (col+t2 > r0g) v0 = -1e30f;
                    if (col+t2 > r1g) v1 = -1e30f;
                }
                s[j][t2] = v0;  s[j][2+t2] = v1;
                rm0 = fmaxf(rm0, v0); rm1 = fmaxf(rm1, v1);
            }
        }
        #pragma unroll
        for (int off = 1; off <= 2; off <<= 1){
            rm0 = fmaxf(rm0, __shfl_xor_sync(0xffffffffu, rm0, off));
            rm1 = fmaxf(rm1, __shfl_xor_sync(0xffffffffu, rm1, off));
        }
        const float mn0 = fmaxf(m0, rm0), mn1 = fmaxf(m1, rm1);
        const float alpha0 = __expf(m0 - mn0), alpha1 = __expf(m1 - mn1);
        m0 = mn0; m1 = mn1;

        float rs0 = 0.f, rs1 = 0.f;
        #pragma unroll
        for (int j = 0; j < 8; j++){
            float p0 = __expf(s[j][0] - mn0);
            float p1 = __expf(s[j][1] - mn0);
            float p2 = __expf(s[j][2] - mn1);
            float p3 = __expf(s[j][3] - mn1);
            rs0 += p0 + p1;  rs1 += p2 + p3;
            *(float2*)&KP[(mB+g  )*ATS + j*8 + 2*c] = make_float2(tf32r(p0), tf32r(p1));
            *(float2*)&KP[(mB+g+8)*ATS + j*8 + 2*c] = make_float2(tf32r(p2), tf32r(p3));
        }
        #pragma unroll
        for (int off = 1; off <= 2; off <<= 1){
            rs0 += __shfl_xor_sync(0xffffffffu, rs0, off);
            rs1 += __shfl_xor_sync(0xffffffffu, rs1, off);
        }
        l0 = l0*alpha0 + rs0;
        l1 = l1*alpha1 + rs1;

        #pragma unroll
        for (int j = 0; j < 8; j++){
            o[j][0] *= alpha0; o[j][1] *= alpha0;
            o[j][2] *= alpha1; o[j][3] *= alpha1;
        }
        __syncwarp();

        #pragma unroll
        for (int kk = 0; kk < 8; kk++){
            const uint32_t a0 = __float_as_uint(KP[(mB+g  )*ATS + kk*8 + c    ]);
            const uint32_t a1 = __float_as_uint(KP[(mB+g+8)*ATS + kk*8 + c    ]);
            const uint32_t a2 = __float_as_uint(KP[(mB+g  )*ATS + kk*8 + c + 4]);
            const uint32_t a3 = __float_as_uint(KP[(mB+g+8)*ATS + kk*8 + c + 4]);
            #pragma unroll
            for (int j = 0; j < 8; j++){
                const uint32_t b0 = __float_as_uint(Vt[(j*8+g)*ATS + kk*8 + c    ]);
                const uint32_t b1 = __float_as_uint(Vt[(j*8+g)*ATS + kk*8 + c + 4]);
                mma_tf32(o[j], a0, a1, a2, a3, b0, b1);
            }
        }
    }

    const float inv0 = 1.0f/l0, inv1 = 1.0f/l1;
    #pragma unroll
    for (int j = 0; j < 8; j++){
        const int col = hoff + j*8 + 2*c;
        *(__half2*)(oh + (size_t)(b*NSEQ + r0g)*DD + col) =
            __floats2half2_rn(o[j][0]*inv0, o[j][1]*inv0);
        *(__half2*)(oh + (size_t)(b*NSEQ + r1g)*DD + col) =
            __floats2half2_rn(o[j][2]*inv1, o[j][3]*inv1);
    }
}

// ---------------- launch ----------------
extern "C" void kernel_launch(void* const* d_in, const int* in_sizes, int n_in,
                              void* d_out, int out_size)
{
    const float* x    = (const float*)d_in[0];
    const float* ln1s = (const float*)d_in[1];
    const float* ln1b = (const float*)d_in[2];
    const float* wqkv = (const float*)d_in[3];
    const float* wout = (const float*)d_in[4];
    const float* bout = (const float*)d_in[5];
    const float* ln2s = (const float*)d_in[6];
    const float* ln2b = (const float*)d_in[7];
    const float* w1   = (const float*)d_in[8];
    const float* b1   = (const float*)d_in[9];
    const float* w2   = (const float*)d_in[10];
    const float* b2   = (const float*)d_in[11];
    float* out = (float*)d_out;

    float *p_qkv, *p_x1;
    __half *p_xn, *p_oh, *p_xn2, *p_y;
    __half *p_wqkvh, *p_wouth, *p_w1h, *p_w2h;
    cudaGetSymbolAddress((void**)&p_xn , g_xn );
    cudaGetSymbolAddress((void**)&p_qkv, g_qkv);
    cudaGetSymbolAddress((void**)&p_oh , g_oh );
    cudaGetSymbolAddress((void**)&p_x1 , g_x1 );
    cudaGetSymbolAddress((void**)&p_xn2, g_xn2);
    cudaGetSymbolAddress((void**)&p_y  , g_y  );
    cudaGetSymbolAddress((void**)&p_wqkvh, g_wqkvh);
    cudaGetSymbolAddress((void**)&p_wouth, g_wouth);
    cudaGetSymbolAddress((void**)&p_w1h  , g_w1h  );
    cudaGetSymbolAddress((void**)&p_w2h  , g_w2h  );

    const int attn_smem = 3*64*ATS*sizeof(float);
    cudaFuncSetAttribute(attn_tc_kernel, cudaFuncAttributeMaxDynamicSharedMemorySize, attn_smem);
    const int gemm_smem = 2*NSTG*128*HSTR*sizeof(__half);   // 61440 B
    cudaFuncSetAttribute(hgemm_kernel<0>, cudaFuncAttributeMaxDynamicSharedMemorySize, gemm_smem);
    cudaFuncSetAttribute(hgemm_kernel<1>, cudaFuncAttributeMaxDynamicSharedMemorySize, gemm_smem);
    cudaFuncSetAttribute(hgemm_kernel<2>, cudaFuncAttributeMaxDynamicSharedMemorySize, gemm_smem);

    // weight prep: transpose [K][N] -> [N][K] + fp16
    wtrans_h_kernel<<<dim3(3*DD/32, DD/32),256>>>(wqkv, p_wqkvh, DD, 3*DD);
    wtrans_h_kernel<<<dim3(DD/32,   DD/32),256>>>(wout, p_wouth, DD, DD);
    wtrans_h_kernel<<<dim3(2*DD/32, DD/32),256>>>(w1,   p_w1h,   DD, 2*DD);
    wtrans_h_kernel<<<dim3(DD/32, 2*DD/32),256>>>(w2,   p_w2h,   2*DD, DD);

    // LN1 -> fp16
    ln_kernel<<<MM,256>>>(x, ln1s, ln1b, p_xn);
    // QKV (fp16 mma) -> fp32 tf32-rounded for attention
    hgemm_kernel<0><<<dim3(3*DD/128, MM/128),256,gemm_smem>>>(p_xn, p_wqkvh, p_qkv, nullptr,
                                                              MM, 3*DD, DD, nullptr, nullptr);
    // causal attention (tf32) -> fp16 output
    attn_tc_kernel<<<dim3(NSEQ/64, BB*NH),128,attn_smem>>>(p_qkv, p_oh);
    // out-proj + residual (fp16 mma) -> fp32
    hgemm_kernel<1><<<dim3(DD/128, MM/128),256,gemm_smem>>>(p_oh, p_wouth, p_x1, nullptr,
                                                            MM, DD, DD, bout, x);
    // LN2 -> fp16
    ln_kernel<<<MM,256>>>(p_x1, ln2s, ln2b, p_xn2);
    // MLP up + GELU (fp16 mma) -> fp16
    hgemm_kernel<2><<<dim3(2*DD/128, MM/128),256,gemm_smem>>>(p_xn2, p_w1h, nullptr, p_y,
                                                              MM, 2*DD, DD, b1, nullptr);
    // MLP down + residual (fp16 mma, K=2048) -> out fp32
    hgemm_kernel<1><<<dim3(DD/128, MM/128),256,gemm_smem>>>(p_y, p_w2h, out, nullptr,
                                                            MM, DD, 2*DD, b2, p_x1);
}

// round 12
// speedup vs baseline: 2.1952x; 1.1754x over previous
#include <cuda_runtime.h>
#include <cuda_fp16.h>
#include <math.h>
#include <stdint.h>

#define BB 2
#define NSEQ 2048
#define DD 1024
#define NH 16
#define HS 64
#define MM (BB*NSEQ)   // 4096 rows

// ---------------- scratch (allocation-free, __device__ globals) ----------------
__device__ __align__(16) __half g_xn [(size_t)MM*DD];      // LN1 out fp16
__device__ __align__(16) __half g_qkv[(size_t)MM*3*DD];    // QKV fp16
__device__ __align__(16) __half g_oh [(size_t)MM*DD];      // attn out fp16
__device__ float g_x1 [(size_t)MM*DD];                      // residual fp32
__device__ __align__(16) __half g_xn2[(size_t)MM*DD];      // LN2 out fp16
__device__ __align__(16) __half g_y  [(size_t)MM*2*DD];    // MLP hidden fp16
// transposed fp16 weights [N][K]
__device__ __align__(16) __half g_wqkvh[(size_t)3*DD*DD];
__device__ __align__(16) __half g_wouth[(size_t)DD*DD];
__device__ __align__(16) __half g_w1h  [(size_t)2*DD*DD];
__device__ __align__(16) __half g_w2h  [(size_t)DD*2*DD];

__device__ __forceinline__ float gelu_tanh(float x){
    float u = 0.7978845608028654f * (x + 0.044715f*x*x*x);
    float t = 1.0f - 2.0f/(__expf(2.0f*u)+1.0f);
    return 0.5f*x*(1.0f+t);
}

__device__ __forceinline__ void cp_async16(void* smem, const void* gmem){
    unsigned s = (unsigned)__cvta_generic_to_shared(smem);
    asm volatile("cp.async.cg.shared.global [%0], [%1], 16;" :: "r"(s), "l"(gmem));
}
__device__ __forceinline__ void cp_commit(){ asm volatile("cp.async.commit_group;"); }
template<int N> __device__ __forceinline__ void cp_wait(){ asm volatile("cp.async.wait_group %0;" :: "n"(N)); }

__device__ __forceinline__ void mma_f16(float c[4], uint32_t a0, uint32_t a1,
                                        uint32_t a2, uint32_t a3,
                                        uint32_t b0, uint32_t b1){
    asm volatile(
        "mma.sync.aligned.m16n8k16.row.col.f32.f16.f16.f32 "
        "{%0,%1,%2,%3},{%4,%5,%6,%7},{%8,%9},{%0,%1,%2,%3};"
        : "+f"(c[0]), "+f"(c[1]), "+f"(c[2]), "+f"(c[3])
        : "r"(a0), "r"(a1), "r"(a2), "r"(a3), "r"(b0), "r"(b1));
}

// ---------------- weight prep: W[K][N] fp32 -> Wh[N][K] fp16 ----------------
__global__ __launch_bounds__(256) void wtrans_h_kernel(const float* __restrict__ W,
                                                       __half* __restrict__ Wh,
                                                       int K, int N)
{
    __shared__ float tile[32][33];
    const int k0 = blockIdx.y*32, n0 = blockIdx.x*32;
    const int tx = threadIdx.x & 31, ty = threadIdx.x >> 5;
    for (int r = ty; r < 32; r += 8)
        tile[r][tx] = W[(size_t)(k0+r)*N + n0 + tx];
    __syncthreads();
    for (int r = ty; r < 32; r += 8)
        Wh[(size_t)(n0+r)*K + k0 + tx] = __float2half_rn(tile[tx][r]);
}

// ---------------- LayerNorm -> fp16 ----------------
__global__ __launch_bounds__(256) void ln_kernel(const float* __restrict__ x,
        const float* __restrict__ sc, const float* __restrict__ bi,
        __half* __restrict__ out)
{
    const int row = blockIdx.x;
    const int t = threadIdx.x;
    const float4 v = ((const float4*)(x + (size_t)row*DD))[t];
    float s  = v.x+v.y+v.z+v.w;
    float sq = v.x*v.x+v.y*v.y+v.z*v.z+v.w*v.w;
    #pragma unroll
    for (int o=16;o>0;o>>=1){
        s  += __shfl_xor_sync(0xffffffffu,s ,o);
        sq += __shfl_xor_sync(0xffffffffu,sq,o);
    }
    __shared__ float ss[8], sqs[8];
    const int warp=t>>5, lane=t&31;
    if (lane==0){ ss[warp]=s; sqs[warp]=sq; }
    __syncthreads();
    if (t==0){
        float a=0.f,b=0.f;
        #pragma unroll
        for(int i=0;i<8;i++){a+=ss[i]; b+=sqs[i];}
        ss[0]=a; sqs[0]=b;
    }
    __syncthreads();
    const float mean = ss[0]*(1.0f/DD);
    const float var  = sqs[0]*(1.0f/DD) - mean*mean;
    const float inv  = rsqrtf(var + 1e-6f);
    const float4 sc4 = ((const float4*)sc)[t];
    const float4 bi4 = ((const float4*)bi)[t];
    __half2* p = (__half2*)(out + (size_t)row*DD + 4*t);
    p[0] = __floats2half2_rn((v.x-mean)*inv*sc4.x + bi4.x,
                             (v.y-mean)*inv*sc4.y + bi4.y);
    p[1] = __floats2half2_rn((v.z-mean)*inv*sc4.z + bi4.z,
                             (v.w-mean)*inv*sc4.w + bi4.w);
}

// ---------------- FP16 GEMM 128x128x32, m16n8k16, 3-stage pipeline ----------------
// EPI: 0 = Ch=fp16(acc) ; 1 = C=acc+bias+res fp32 ; 2 = Ch=fp16(gelu(acc+bias))
#define HSTR 40     // fp16 units per row (80 B)
#define NSTG 3
template<int EPI>
__global__ __launch_bounds__(256) void hgemm_kernel(
    const __half* __restrict__ A, const __half* __restrict__ B,
    float* __restrict__ C, __half* __restrict__ Ch, int M, int N, int K,
    const float* __restrict__ bias, const float* __restrict__ res)
{
    extern __shared__ __half smh[];
    __half (*As)[128][HSTR] = (__half(*)[128][HSTR])smh;
    __half (*Bs)[128][HSTR] = (__half(*)[128][HSTR])(smh + (size_t)NSTG*128*HSTR);

    const int tid  = threadIdx.x;
    const int lane = tid & 31;
    const int warp = tid >> 5;
    const int wm = warp >> 1;
    const int wn = warp & 1;
    const int mB = wm*32;
    const int nB = wn*64;
    const int bm = blockIdx.y*128;
    const int bn = blockIdx.x*128;

    const int lr = tid >> 1;
    const int c0 = (tid & 1);

    const __half* Ag = A + (size_t)(bm + lr)*K + c0*8;
    const __half* Bg = B + (size_t)(bn + lr)*K + c0*8;

    const int nk = K >> 5;

    #pragma unroll
    for (int p = 0; p < 2; p++){
        const int ko = p << 5;
        cp_async16(&As[p][lr][c0*8     ], Ag + ko);
        cp_async16(&As[p][lr][c0*8 + 16], Ag + ko + 16);
        cp_async16(&Bs[p][lr][c0*8     ], Bg + ko);
        cp_async16(&Bs[p][lr][c0*8 + 16], Bg + ko + 16);
        cp_commit();
    }

    float acc[2][8][4] = {};
    const int g = lane >> 2;
    const int c = lane & 3;

    int cur = 0;
    for (int kt = 0; kt < nk; kt++){
        cp_wait<1>();
        __syncthreads();

        if (kt + 2 < nk){
            int nxt = cur + 2;
            if (nxt >= NSTG) nxt -= NSTG;
            const int ko = (kt+2) << 5;
            cp_async16(&As[nxt][lr][c0*8     ], Ag + ko);
            cp_async16(&As[nxt][lr][c0*8 + 16], Ag + ko + 16);
            cp_async16(&Bs[nxt][lr][c0*8     ], Bg + ko);
            cp_async16(&Bs[nxt][lr][c0*8 + 16], Bg + ko + 16);
            cp_commit();
        }

        #pragma unroll
        for (int kk = 0; kk < 2; kk++){
            const int kb = kk*16 + 2*c;
            uint32_t af[2][4], bf[8][2];
            #pragma unroll
            for (int i = 0; i < 2; i++){
                const int r0 = mB + i*16 + g;
                af[i][0] = *(const uint32_t*)&As[cur][r0    ][kb    ];
                af[i][1] = *(const uint32_t*)&As[cur][r0 + 8][kb    ];
                af[i][2] = *(const uint32_t*)&As[cur][r0    ][kb + 8];
                af[i][3] = *(const uint32_t*)&As[cur][r0 + 8][kb + 8];
            }
            #pragma unroll
            for (int j = 0; j < 8; j++){
                const int n = nB + j*8 + g;
                bf[j][0] = *(const uint32_t*)&Bs[cur][n][kb    ];
                bf[j][1] = *(const uint32_t*)&Bs[cur][n][kb + 8];
            }
            #pragma unroll
            for (int i = 0; i < 2; i++)
                #pragma unroll
                for (int j = 0; j < 8; j++)
                    mma_f16(acc[i][j], af[i][0], af[i][1], af[i][2], af[i][3],
                            bf[j][0], bf[j][1]);
        }
        cur = (cur + 1 == NSTG) ? 0 : cur + 1;
    }

    #pragma unroll
    for (int i = 0; i < 2; i++){
        const int row = bm + mB + i*16 + g;
        #pragma unroll
        for (int j = 0; j < 8; j++){
            const int col = bn + nB + j*8 + c*2;
            float v0 = acc[i][j][0], v1 = acc[i][j][1];
            float v2 = acc[i][j][2], v3 = acc[i][j][3];
            const size_t o0 = (size_t)row*N + col;
            const size_t o1 = (size_t)(row+8)*N + col;
            if (EPI == 0){
                *(__half2*)(Ch + o0) = __floats2half2_rn(v0, v1);
                *(__half2*)(Ch + o1) = __floats2half2_rn(v2, v3);
            } else if (EPI == 1){
                const float b0 = bias[col], b1 = bias[col+1];
                *(float2*)(C + o0) = make_float2(v0 + b0 + res[o0], v1 + b1 + res[o0+1]);
                *(float2*)(C + o1) = make_float2(v2 + b0 + res[o1], v3 + b1 + res[o1+1]);
            } else {
                const float b0 = bias[col], b1 = bias[col+1];
                *(__half2*)(Ch + o0) = __floats2half2_rn(gelu_tanh(v0 + b0), gelu_tanh(v1 + b1));
                *(__half2*)(Ch + o1) = __floats2half2_rn(gelu_tanh(v2 + b0), gelu_tanh(v3 + b1));
            }
        }
    }
}

// ---------------- Causal flash attention, full fp16 mma ----------------
// Qs/KP stride 72 halves (conflict-free fragment loads); Vt stride 68.
#define HSA 72
#define HSV 68
__global__ __launch_bounds__(128, 4) void attn_h_kernel(const __half* __restrict__ qkv,
                                                        __half* __restrict__ oh)
{
    extern __shared__ __half sh[];
    __half* Qs = sh;                  // [64][HSA]  Q[row][d]
    __half* KP = sh + 64*HSA;         // [64][HSA]  K[key][d], then P[row][key]
    __half* Vt = sh + 2*64*HSA;       // [64][HSV]  V^T[d][key]

    const int qt = gridDim.x - 1 - blockIdx.x;
    const int bh = blockIdx.y;
    const int b = bh >> 4;
    const int h = bh & 15;
    const int tid = threadIdx.x;
    const int lane = tid & 31;
    const int warp = tid >> 5;
    const int mB = warp * 16;
    const int g = lane >> 2;
    const int c = lane & 3;
    const size_t base = (size_t)b * NSEQ * (3*DD);
    const int hoff = h * HS;

    // load Q tile (64 rows x 64 halves, 16B chunks)
    for (int i = tid; i < 512; i += 128){
        const int row = i >> 3, ch = i & 7;
        *(uint4*)&Qs[row*HSA + ch*8] =
            *(const uint4*)(qkv + base + (size_t)(qt*64+row)*(3*DD) + hoff + ch*8);
    }
    __syncthreads();

    // hoist Q fragments (4 k-steps of 16)
    uint32_t qa[4][4];
    #pragma unroll
    for (int kk = 0; kk < 4; kk++){
        qa[kk][0] = *(const uint32_t*)&Qs[(mB+g  )*HSA + kk*16 + 2*c    ];
        qa[kk][1] = *(const uint32_t*)&Qs[(mB+g+8)*HSA + kk*16 + 2*c    ];
        qa[kk][2] = *(const uint32_t*)&Qs[(mB+g  )*HSA + kk*16 + 2*c + 8];
        qa[kk][3] = *(const uint32_t*)&Qs[(mB+g+8)*HSA + kk*16 + 2*c + 8];
    }

    float o[8][4] = {};
    float m0=-1e30f, m1=-1e30f, l0=0.f, l1=0.f;

    const int r0g = qt*64 + mB + g;
    const int r1g = r0g + 8;

    for (int jt = 0; jt <= qt; jt++){
        __syncthreads();
        for (int i = tid; i < 512; i += 128){
            const int row = i >> 3, ch = i & 7;
            const size_t roff = base + (size_t)(jt*64+row)*(3*DD) + hoff + ch*8;
            *(uint4*)&KP[row*HSA + ch*8] = *(const uint4*)(qkv + roff + DD);
            uint4 vv = *(const uint4*)(qkv + roff + 2*DD);
            const __half* vh = (const __half*)&vv;
            #pragma unroll
            for (int d = 0; d < 8; d++)
                Vt[(ch*8 + d)*HSV + row] = vh[d];
        }
        __syncthreads();

        // S = Q K^T
        float s[8][4] = {};
        #pragma unroll
        for (int kk = 0; kk < 4; kk++){
            #pragma unroll
            for (int j = 0; j < 8; j++){
                const uint32_t b0 = *(const uint32_t*)&KP[(j*8+g)*HSA + kk*16 + 2*c    ];
                const uint32_t b1 = *(const uint32_t*)&KP[(j*8+g)*HSA + kk*16 + 2*c + 8];
                mma_f16(s[j], qa[kk][0], qa[kk][1], qa[kk][2], qa[kk][3], b0, b1);
            }
        }
        __syncthreads();   // all warps done reading K before P overwrite

        // scale + mask + row max
        float rm0 = -1e30f, rm1 = -1e30f;
        #pragma unroll
        for (int j = 0; j < 8; j++){
            const int col = jt*64 + j*8 + 2*c;
            #pragma unroll
            for (int t2 = 0; t2 < 2; t2++){
                float v0 = s[j][t2]*0.125f;
                float v1 = s[j][2+t2]*0.125f;
                if (jt == qt){
                    if (col+t2 > r0g) v0 = -1e30f;
                    if (col+t2 > r1g) v1 = -1e30f;
                }
                s[j][t2] = v0;  s[j][2+t2] = v1;
                rm0 = fmaxf(rm0, v0); rm1 = fmaxf(rm1, v1);
            }
        }
        #pragma unroll
        for (int off = 1; off <= 2; off <<= 1){
            rm0 = fmaxf(rm0, __shfl_xor_sync(0xffffffffu, rm0, off));
            rm1 = fmaxf(rm1, __shfl_xor_sync(0xffffffffu, rm1, off));
        }
        const float mn0 = fmaxf(m0, rm0), mn1 = fmaxf(m1, rm1);
        const float alpha0 = __expf(m0 - mn0), alpha1 = __expf(m1 - mn1);
        m0 = mn0; m1 = mn1;

        float rs0 = 0.f, rs1 = 0.f;
        #pragma unroll
        for (int j = 0; j < 8; j++){
            float p0 = __expf(s[j][0] - mn0);
            float p1 = __expf(s[j][1] - mn0);
            float p2 = __expf(s[j][2] - mn1);
            float p3 = __expf(s[j][3] - mn1);
            rs0 += p0 + p1;  rs1 += p2 + p3;
            *(__half2*)&KP[(mB+g  )*HSA + j*8 + 2*c] = __floats2half2_rn(p0, p1);
            *(__half2*)&KP[(mB+g+8)*HSA + j*8 + 2*c] = __floats2half2_rn(p2, p3);
        }
        #pragma unroll
        for (int off = 1; off <= 2; off <<= 1){
            rs0 += __shfl_xor_sync(0xffffffffu, rs0, off);
            rs1 += __shfl_xor_sync(0xffffffffu, rs1, off);
        }
        l0 = l0*alpha0 + rs0;
        l1 = l1*alpha1 + rs1;

        #pragma unroll
        for (int j = 0; j < 8; j++){
            o[j][0] *= alpha0; o[j][1] *= alpha0;
            o[j][2] *= alpha1; o[j][3] *= alpha1;
        }
        __syncwarp();      // P rows are warp-private

        // O += P @ V
        #pragma unroll
        for (int kk = 0; kk < 4; kk++){
            const uint32_t a0 = *(const uint32_t*)&KP[(mB+g  )*HSA + kk*16 + 2*c    ];
            const uint32_t a1 = *(const uint32_t*)&KP[(mB+g+8)*HSA + kk*16 + 2*c    ];
            const uint32_t a2 = *(const uint32_t*)&KP[(mB+g  )*HSA + kk*16 + 2*c + 8];
            const uint32_t a3 = *(const uint32_t*)&KP[(mB+g+8)*HSA + kk*16 + 2*c + 8];
            #pragma unroll
            for (int j = 0; j < 8; j++){
                const uint32_t b0 = *(const uint32_t*)&Vt[(j*8+g)*HSV + kk*16 + 2*c    ];
                const uint32_t b1 = *(const uint32_t*)&Vt[(j*8+g)*HSV + kk*16 + 2*c + 8];
                mma_f16(o[j], a0, a1, a2, a3, b0, b1);
            }
        }
    }

    const float inv0 = 1.0f/l0, inv1 = 1.0f/l1;
    #pragma unroll
    for (int j = 0; j < 8; j++){
        const int col = hoff + j*8 + 2*c;
        *(__half2*)(oh + (size_t)(b*NSEQ + r0g)*DD + col) =
            __floats2half2_rn(o[j][0]*inv0, o[j][1]*inv0);
        *(__half2*)(oh + (size_t)(b*NSEQ + r1g)*DD + col) =
            __floats2half2_rn(o[j][2]*inv1, o[j][3]*inv1);
    }
}

// ---------------- launch ----------------
extern "C" void kernel_launch(void* const* d_in, const int* in_sizes, int n_in,
                              void* d_out, int out_size)
{
    const float* x    = (const float*)d_in[0];
    const float* ln1s = (const float*)d_in[1];
    const float* ln1b = (const float*)d_in[2];
    const float* wqkv = (const float*)d_in[3];
    const float* wout = (const float*)d_in[4];
    const float* bout = (const float*)d_in[5];
    const float* ln2s = (const float*)d_in[6];
    const float* ln2b = (const float*)d_in[7];
    const float* w1   = (const float*)d_in[8];
    const float* b1   = (const float*)d_in[9];
    const float* w2   = (const float*)d_in[10];
    const float* b2   = (const float*)d_in[11];
    float* out = (float*)d_out;

    float *p_x1;
    __half *p_xn, *p_qkv, *p_oh, *p_xn2, *p_y;
    __half *p_wqkvh, *p_wouth, *p_w1h, *p_w2h;
    cudaGetSymbolAddress((void**)&p_xn , g_xn );
    cudaGetSymbolAddress((void**)&p_qkv, g_qkv);
    cudaGetSymbolAddress((void**)&p_oh , g_oh );
    cudaGetSymbolAddress((void**)&p_x1 , g_x1 );
    cudaGetSymbolAddress((void**)&p_xn2, g_xn2);
    cudaGetSymbolAddress((void**)&p_y  , g_y  );
    cudaGetSymbolAddress((void**)&p_wqkvh, g_wqkvh);
    cudaGetSymbolAddress((void**)&p_wouth, g_wouth);
    cudaGetSymbolAddress((void**)&p_w1h  , g_w1h  );
    cudaGetSymbolAddress((void**)&p_w2h  , g_w2h  );

    const int attn_smem = (2*64*HSA + 64*HSV)*sizeof(__half);   // 27136 B
    cudaFuncSetAttribute(attn_h_kernel, cudaFuncAttributeMaxDynamicSharedMemorySize, attn_smem);
    const int gemm_smem = 2*NSTG*128*HSTR*sizeof(__half);       // 61440 B
    cudaFuncSetAttribute(hgemm_kernel<0>, cudaFuncAttributeMaxDynamicSharedMemorySize, gemm_smem);
    cudaFuncSetAttribute(hgemm_kernel<1>, cudaFuncAttributeMaxDynamicSharedMemorySize, gemm_smem);
    cudaFuncSetAttribute(hgemm_kernel<2>, cudaFuncAttributeMaxDynamicSharedMemorySize, gemm_smem);

    // weight prep
    wtrans_h_kernel<<<dim3(3*DD/32, DD/32),256>>>(wqkv, p_wqkvh, DD, 3*DD);
    wtrans_h_kernel<<<dim3(DD/32,   DD/32),256>>>(wout, p_wouth, DD, DD);
    wtrans_h_kernel<<<dim3(2*DD/32, DD/32),256>>>(w1,   p_w1h,   DD, 2*DD);
    wtrans_h_kernel<<<dim3(DD/32, 2*DD/32),256>>>(w2,   p_w2h,   2*DD, DD);

    // LN1 -> fp16
    ln_kernel<<<MM,256>>>(x, ln1s, ln1b, p_xn);
    // QKV (fp16 mma) -> fp16
    hgemm_kernel<0><<<dim3(3*DD/128, MM/128),256,gemm_smem>>>(p_xn, p_wqkvh, nullptr, p_qkv,
                                                              MM, 3*DD, DD, nullptr, nullptr);
    // causal attention (fp16) -> fp16
    attn_h_kernel<<<dim3(NSEQ/64, BB*NH),128,attn_smem>>>(p_qkv, p_oh);
    // out-proj + residual (fp16 mma) -> fp32
    hgemm_kernel<1><<<dim3(DD/128, MM/128),256,gemm_smem>>>(p_oh, p_wouth, p_x1, nullptr,
                                                            MM, DD, DD, bout, x);
    // LN2 -> fp16
    ln_kernel<<<MM,256>>>(p_x1, ln2s, ln2b, p_xn2);
    // MLP up + GELU -> fp16
    hgemm_kernel<2><<<dim3(2*DD/128, MM/128),256,gemm_smem>>>(p_xn2, p_w1h, nullptr, p_y,
                                                              MM, 2*DD, DD, b1, nullptr);
    // MLP down + residual -> out fp32
    hgemm_kernel<1><<<dim3(DD/128, MM/128),256,gemm_smem>>>(p_y, p_w2h, out, nullptr,
                                                            MM, DD, 2*DD, b2, p_x1);
}

// round 13
// speedup vs baseline: 2.2374x; 1.0192x over previous
#include <cuda_runtime.h>
#include <cuda_fp16.h>
#include <math.h>
#include <stdint.h>

#define BB 2
#define NSEQ 2048
#define DD 1024
#define NH 16
#define HS 64
#define MM (BB*NSEQ)   // 4096 rows

// ---------------- scratch (allocation-free, __device__ globals) ----------------
__device__ __align__(16) __half g_xn [(size_t)MM*DD];      // LN1 out fp16
__device__ __align__(16) __half g_qkv[(size_t)MM*3*DD];    // QKV fp16
__device__ __align__(16) __half g_oh [(size_t)MM*DD];      // attn out fp16
__device__ float g_x1 [(size_t)MM*DD];                      // residual fp32
__device__ __align__(16) __half g_xn2[(size_t)MM*DD];      // LN2 out fp16
__device__ __align__(16) __half g_y  [(size_t)MM*2*DD];    // MLP hidden fp16
// transposed fp16 weights [N][K]
__device__ __align__(16) __half g_wqkvh[(size_t)3*DD*DD];
__device__ __align__(16) __half g_wouth[(size_t)DD*DD];
__device__ __align__(16) __half g_w1h  [(size_t)2*DD*DD];
__device__ __align__(16) __half g_w2h  [(size_t)DD*2*DD];

__device__ __forceinline__ float gelu_tanh(float x){
    float u = 0.7978845608028654f * (x + 0.044715f*x*x*x);
    float t = 1.0f - 2.0f/(__expf(2.0f*u)+1.0f);
    return 0.5f*x*(1.0f+t);
}

__device__ __forceinline__ void cp_async16(void* smem, const void* gmem){
    unsigned s = (unsigned)__cvta_generic_to_shared(smem);
    asm volatile("cp.async.cg.shared.global [%0], [%1], 16;" :: "r"(s), "l"(gmem));
}
__device__ __forceinline__ void cp_commit(){ asm volatile("cp.async.commit_group;"); }
template<int N> __device__ __forceinline__ void cp_wait(){ asm volatile("cp.async.wait_group %0;" :: "n"(N)); }

__device__ __forceinline__ void mma_f16(float c[4], uint32_t a0, uint32_t a1,
                                        uint32_t a2, uint32_t a3,
                                        uint32_t b0, uint32_t b1){
    asm volatile(
        "mma.sync.aligned.m16n8k16.row.col.f32.f16.f16.f32 "
        "{%0,%1,%2,%3},{%4,%5,%6,%7},{%8,%9},{%0,%1,%2,%3};"
        : "+f"(c[0]), "+f"(c[1]), "+f"(c[2]), "+f"(c[3])
        : "r"(a0), "r"(a1), "r"(a2), "r"(a3), "r"(b0), "r"(b1));
}

// ---------------- weight prep: W[K][N] fp32 -> Wh[N][K] fp16 ----------------
__global__ __launch_bounds__(256) void wtrans_h_kernel(const float* __restrict__ W,
                                                       __half* __restrict__ Wh,
                                                       int K, int N)
{
    __shared__ float tile[32][33];
    const int k0 = blockIdx.y*32, n0 = blockIdx.x*32;
    const int tx = threadIdx.x & 31, ty = threadIdx.x >> 5;
    for (int r = ty; r < 32; r += 8)
        tile[r][tx] = W[(size_t)(k0+r)*N + n0 + tx];
    __syncthreads();
    for (int r = ty; r < 32; r += 8)
        Wh[(size_t)(n0+r)*K + k0 + tx] = __float2half_rn(tile[tx][r]);
}

// ---------------- LayerNorm -> fp16 ----------------
__global__ __launch_bounds__(256) void ln_kernel(const float* __restrict__ x,
        const float* __restrict__ sc, const float* __restrict__ bi,
        __half* __restrict__ out)
{
    const int row = blockIdx.x;
    const int t = threadIdx.x;
    const float4 v = ((const float4*)(x + (size_t)row*DD))[t];
    float s  = v.x+v.y+v.z+v.w;
    float sq = v.x*v.x+v.y*v.y+v.z*v.z+v.w*v.w;
    #pragma unroll
    for (int o=16;o>0;o>>=1){
        s  += __shfl_xor_sync(0xffffffffu,s ,o);
        sq += __shfl_xor_sync(0xffffffffu,sq,o);
    }
    __shared__ float ss[8], sqs[8];
    const int warp=t>>5, lane=t&31;
    if (lane==0){ ss[warp]=s; sqs[warp]=sq; }
    __syncthreads();
    if (t==0){
        float a=0.f,b=0.f;
        #pragma unroll
        for(int i=0;i<8;i++){a+=ss[i]; b+=sqs[i];}
        ss[0]=a; sqs[0]=b;
    }
    __syncthreads();
    const float mean = ss[0]*(1.0f/DD);
    const float var  = sqs[0]*(1.0f/DD) - mean*mean;
    const float inv  = rsqrtf(var + 1e-6f);
    const float4 sc4 = ((const float4*)sc)[t];
    const float4 bi4 = ((const float4*)bi)[t];
    __half2* p = (__half2*)(out + (size_t)row*DD + 4*t);
    p[0] = __floats2half2_rn((v.x-mean)*inv*sc4.x + bi4.x,
                             (v.y-mean)*inv*sc4.y + bi4.y);
    p[1] = __floats2half2_rn((v.z-mean)*inv*sc4.z + bi4.z,
                             (v.w-mean)*inv*sc4.w + bi4.w);
}

// ---------------- FP16 GEMM: CTA 128x256, warp 64x64 (I=4,J=8), 3-stage ----------------
// A [M][K] fp16; B = Wh [N][K] fp16. Scalar b32 operand loads.
// EPI: 0 = Ch=fp16(acc) ; 1 = C=acc+bias+res fp32 ; 2 = Ch=fp16(gelu(acc+bias))
#define HSTR 40     // fp16 units per row (80 B)
#define NSTG 3
#define TM 128
#define TN 256
template<int EPI>
__global__ __launch_bounds__(256,1) void hgemm_kernel(
    const __half* __restrict__ A, const __half* __restrict__ B,
    float* __restrict__ C, __half* __restrict__ Ch, int M, int N, int K,
    const float* __restrict__ bias, const float* __restrict__ res)
{
    extern __shared__ __half smh[];
    __half (*As)[TM][HSTR] = (__half(*)[TM][HSTR])smh;
    __half (*Bs)[TN][HSTR] = (__half(*)[TN][HSTR])(smh + (size_t)NSTG*TM*HSTR);

    const int tid  = threadIdx.x;
    const int lane = tid & 31;
    const int warp = tid >> 5;
    const int wm = warp >> 2;        // 0..1
    const int wn = warp & 3;         // 0..3
    const int mB = wm*64;
    const int nB = wn*64;
    const int bm = blockIdx.y*TM;
    const int bn = blockIdx.x*TN;

    const int lr = tid >> 1;         // 0..127
    const int c0 = (tid & 1);        // 0/1

    const __half* Ag  = A + (size_t)(bm + lr)*K + c0*8;
    const __half* Bg0 = B + (size_t)(bn + lr)*K + c0*8;
    const __half* Bg1 = B + (size_t)(bn + lr + 128)*K + c0*8;

    const int nk = K >> 5;

    #pragma unroll
    for (int p = 0; p < 2; p++){
        const int ko = p << 5;
        cp_async16(&As[p][lr][c0*8     ], Ag + ko);
        cp_async16(&As[p][lr][c0*8 + 16], Ag + ko + 16);
        cp_async16(&Bs[p][lr][c0*8     ], Bg0 + ko);
        cp_async16(&Bs[p][lr][c0*8 + 16], Bg0 + ko + 16);
        cp_async16(&Bs[p][lr + 128][c0*8     ], Bg1 + ko);
        cp_async16(&Bs[p][lr + 128][c0*8 + 16], Bg1 + ko + 16);
        cp_commit();
    }

    float acc[4][8][4] = {};
    const int g = lane >> 2;
    const int c = lane & 3;

    int cur = 0;
    for (int kt = 0; kt < nk; kt++){
        cp_wait<1>();
        __syncthreads();

        if (kt + 2 < nk){
            int nxt = cur + 2;
            if (nxt >= NSTG) nxt -= NSTG;
            const int ko = (kt+2) << 5;
            cp_async16(&As[nxt][lr][c0*8     ], Ag + ko);
            cp_async16(&As[nxt][lr][c0*8 + 16], Ag + ko + 16);
            cp_async16(&Bs[nxt][lr][c0*8     ], Bg0 + ko);
            cp_async16(&Bs[nxt][lr][c0*8 + 16], Bg0 + ko + 16);
            cp_async16(&Bs[nxt][lr + 128][c0*8     ], Bg1 + ko);
            cp_async16(&Bs[nxt][lr + 128][c0*8 + 16], Bg1 + ko + 16);
            cp_commit();
        }

        #pragma unroll
        for (int kk = 0; kk < 2; kk++){
            const int kb = kk*16 + 2*c;
            uint32_t af[4][4], bf[8][2];
            #pragma unroll
            for (int i = 0; i < 4; i++){
                const int r0 = mB + i*16 + g;
                af[i][0] = *(const uint32_t*)&As[cur][r0    ][kb    ];
                af[i][1] = *(const uint32_t*)&As[cur][r0 + 8][kb    ];
                af[i][2] = *(const uint32_t*)&As[cur][r0    ][kb + 8];
                af[i][3] = *(const uint32_t*)&As[cur][r0 + 8][kb + 8];
            }
            #pragma unroll
            for (int j = 0; j < 8; j++){
                const int n = nB + j*8 + g;
                bf[j][0] = *(const uint32_t*)&Bs[cur][n][kb    ];
                bf[j][1] = *(const uint32_t*)&Bs[cur][n][kb + 8];
            }
            #pragma unroll
            for (int i = 0; i < 4; i++)
                #pragma unroll
                for (int j = 0; j < 8; j++)
                    mma_f16(acc[i][j], af[i][0], af[i][1], af[i][2], af[i][3],
                            bf[j][0], bf[j][1]);
        }
        cur = (cur + 1 == NSTG) ? 0 : cur + 1;
    }

    #pragma unroll
    for (int i = 0; i < 4; i++){
        const int row = bm + mB + i*16 + g;
        #pragma unroll
        for (int j = 0; j < 8; j++){
            const int col = bn + nB + j*8 + c*2;
            float v0 = acc[i][j][0], v1 = acc[i][j][1];
            float v2 = acc[i][j][2], v3 = acc[i][j][3];
            const size_t o0 = (size_t)row*N + col;
            const size_t o1 = (size_t)(row+8)*N + col;
            if (EPI == 0){
                *(__half2*)(Ch + o0) = __floats2half2_rn(v0, v1);
                *(__half2*)(Ch + o1) = __floats2half2_rn(v2, v3);
            } else if (EPI == 1){
                const float b0 = bias[col], b1 = bias[col+1];
                *(float2*)(C + o0) = make_float2(v0 + b0 + res[o0], v1 + b1 + res[o0+1]);
                *(float2*)(C + o1) = make_float2(v2 + b0 + res[o1], v3 + b1 + res[o1+1]);
            } else {
                const float b0 = bias[col], b1 = bias[col+1];
                *(__half2*)(Ch + o0) = __floats2half2_rn(gelu_tanh(v0 + b0), gelu_tanh(v1 + b1));
                *(__half2*)(Ch + o1) = __floats2half2_rn(gelu_tanh(v2 + b0), gelu_tanh(v3 + b1));
            }
        }
    }
}

// ---------------- Causal flash attention, full fp16 mma ----------------
#define HSA 72
#define HSV 68
__global__ __launch_bounds__(128, 4) void attn_h_kernel(const __half* __restrict__ qkv,
                                                        __half* __restrict__ oh)
{
    extern __shared__ __half sh[];
    __half* Qs = sh;
    __half* KP = sh + 64*HSA;
    __half* Vt = sh + 2*64*HSA;

    const int qt = gridDim.x - 1 - blockIdx.x;
    const int bh = blockIdx.y;
    const int b = bh >> 4;
    const int h = bh & 15;
    const int tid = threadIdx.x;
    const int lane = tid & 31;
    const int warp = tid >> 5;
    const int mB = warp * 16;
    const int g = lane >> 2;
    const int c = lane & 3;
    const size_t base = (size_t)b * NSEQ * (3*DD);
    const int hoff = h * HS;

    for (int i = tid; i < 512; i += 128){
        const int row = i >> 3, ch = i & 7;
        *(uint4*)&Qs[row*HSA + ch*8] =
            *(const uint4*)(qkv + base + (size_t)(qt*64+row)*(3*DD) + hoff + ch*8);
    }
    __syncthreads();

    uint32_t qa[4][4];
    #pragma unroll
    for (int kk = 0; kk < 4; kk++){
        qa[kk][0] = *(const uint32_t*)&Qs[(mB+g  )*HSA + kk*16 + 2*c    ];
        qa[kk][1] = *(const uint32_t*)&Qs[(mB+g+8)*HSA + kk*16 + 2*c    ];
        qa[kk][2] = *(const uint32_t*)&Qs[(mB+g  )*HSA + kk*16 + 2*c + 8];
        qa[kk][3] = *(const uint32_t*)&Qs[(mB+g+8)*HSA + kk*16 + 2*c + 8];
    }

    float o[8][4] = {};
    float m0=-1e30f, m1=-1e30f, l0=0.f, l1=0.f;

    const int r0g = qt*64 + mB + g;
    const int r1g = r0g + 8;

    for (int jt = 0; jt <= qt; jt++){
        __syncthreads();
        for (int i = tid; i < 512; i += 128){
            const int row = i >> 3, ch = i & 7;
            const size_t roff = base + (size_t)(jt*64+row)*(3*DD) + hoff + ch*8;
            *(uint4*)&KP[row*HSA + ch*8] = *(const uint4*)(qkv + roff + DD);
            uint4 vv = *(const uint4*)(qkv + roff + 2*DD);
            const __half* vh = (const __half*)&vv;
            #pragma unroll
            for (int d = 0; d < 8; d++)
                Vt[(ch*8 + d)*HSV + row] = vh[d];
        }
        __syncthreads();

        float s[8][4] = {};
        #pragma unroll
        for (int kk = 0; kk < 4; kk++){
            #pragma unroll
            for (int j = 0; j < 8; j++){
                const uint32_t b0 = *(const uint32_t*)&KP[(j*8+g)*HSA + kk*16 + 2*c    ];
                const uint32_t b1 = *(const uint32_t*)&KP[(j*8+g)*HSA + kk*16 + 2*c + 8];
                mma_f16(s[j], qa[kk][0], qa[kk][1], qa[kk][2], qa[kk][3], b0, b1);
            }
        }
        __syncthreads();

        float rm0 = -1e30f, rm1 = -1e30f;
        #pragma unroll
        for (int j = 0; j < 8; j++){
            const int col = jt*64 + j*8 + 2*c;
            #pragma unroll
            for (int t2 = 0; t2 < 2; t2++){
                float v0 = s[j][t2]*0.125f;
                float v1 = s[j][2+t2]*0.125f;
                if (jt == qt){
                    if (col+t2 > r0g) v0 = -1e30f;
                    if (col+t2 > r1g) v1 = -1e30f;
                }
                s[j][t2] = v0;  s[j][2+t2] = v1;
                rm0 = fmaxf(rm0, v0); rm1 = fmaxf(rm1, v1);
            }
        }
        #pragma unroll
        for (int off = 1; off <= 2; off <<= 1){
            rm0 = fmaxf(rm0, __shfl_xor_sync(0xffffffffu, rm0, off));
            rm1 = fmaxf(rm1, __shfl_xor_sync(0xffffffffu, rm1, off));
        }
        const float mn0 = fmaxf(m0, rm0), mn1 = fmaxf(m1, rm1);
        const float alpha0 = __expf(m0 - mn0), alpha1 = __expf(m1 - mn1);
        m0 = mn0; m1 = mn1;

        float rs0 = 0.f, rs1 = 0.f;
        #pragma unroll
        for (int j = 0; j < 8; j++){
            float p0 = __expf(s[j][0] - mn0);
            float p1 = __expf(s[j][1] - mn0);
            float p2 = __expf(s[j][2] - mn1);
            float p3 = __expf(s[j][3] - mn1);
            rs0 += p0 + p1;  rs1 += p2 + p3;
            *(__half2*)&KP[(mB+g  )*HSA + j*8 + 2*c] = __floats2half2_rn(p0, p1);
            *(__half2*)&KP[(mB+g+8)*HSA + j*8 + 2*c] = __floats2half2_rn(p2, p3);
        }
        #pragma unroll
        for (int off = 1; off <= 2; off <<= 1){
            rs0 += __shfl_xor_sync(0xffffffffu, rs0, off);
            rs1 += __shfl_xor_sync(0xffffffffu, rs1, off);
        }
        l0 = l0*alpha0 + rs0;
        l1 = l1*alpha1 + rs1;

        #pragma unroll
        for (int j = 0; j < 8; j++){
            o[j][0] *= alpha0; o[j][1] *= alpha0;
            o[j][2] *= alpha1; o[j][3] *= alpha1;
        }
        __syncwarp();

        #pragma unroll
        for (int kk = 0; kk < 4; kk++){
            const uint32_t a0 = *(const uint32_t*)&KP[(mB+g  )*HSA + kk*16 + 2*c    ];
            const uint32_t a1 = *(const uint32_t*)&KP[(mB+g+8)*HSA + kk*16 + 2*c    ];
            const uint32_t a2 = *(const uint32_t*)&KP[(mB+g  )*HSA + kk*16 + 2*c + 8];
            const uint32_t a3 = *(const uint32_t*)&KP[(mB+g+8)*HSA + kk*16 + 2*c + 8];
            #pragma unroll
            for (int j = 0; j < 8; j++){
                const uint32_t b0 = *(const uint32_t*)&Vt[(j*8+g)*HSV + kk*16 + 2*c    ];
                const uint32_t b1 = *(const uint32_t*)&Vt[(j*8+g)*HSV + kk*16 + 2*c + 8];
                mma_f16(o[j], a0, a1, a2, a3, b0, b1);
            }
        }
    }

    const float inv0 = 1.0f/l0, inv1 = 1.0f/l1;
    #pragma unroll
    for (int j = 0; j < 8; j++){
        const int col = hoff + j*8 + 2*c;
        *(__half2*)(oh + (size_t)(b*NSEQ + r0g)*DD + col) =
            __floats2half2_rn(o[j][0]*inv0, o[j][1]*inv0);
        *(__half2*)(oh + (size_t)(b*NSEQ + r1g)*DD + col) =
            __floats2half2_rn(o[j][2]*inv1, o[j][3]*inv1);
    }
}

// ---------------- launch ----------------
extern "C" void kernel_launch(void* const* d_in, const int* in_sizes, int n_in,
                              void* d_out, int out_size)
{
    const float* x    = (const float*)d_in[0];
    const float* ln1s = (const float*)d_in[1];
    const float* ln1b = (const float*)d_in[2];
    const float* wqkv = (const float*)d_in[3];
    const float* wout = (const float*)d_in[4];
    const float* bout = (const float*)d_in[5];
    const float* ln2s = (const float*)d_in[6];
    const float* ln2b = (const float*)d_in[7];
    const float* w1   = (const float*)d_in[8];
    const float* b1   = (const float*)d_in[9];
    const float* w2   = (const float*)d_in[10];
    const float* b2   = (const float*)d_in[11];
    float* out = (float*)d_out;

    float *p_x1;
    __half *p_xn, *p_qkv, *p_oh, *p_xn2, *p_y;
    __half *p_wqkvh, *p_wouth, *p_w1h, *p_w2h;
    cudaGetSymbolAddress((void**)&p_xn , g_xn );
    cudaGetSymbolAddress((void**)&p_qkv, g_qkv);
    cudaGetSymbolAddress((void**)&p_oh , g_oh );
    cudaGetSymbolAddress((void**)&p_x1 , g_x1 );
    cudaGetSymbolAddress((void**)&p_xn2, g_xn2);
    cudaGetSymbolAddress((void**)&p_y  , g_y  );
    cudaGetSymbolAddress((void**)&p_wqkvh, g_wqkvh);
    cudaGetSymbolAddress((void**)&p_wouth, g_wouth);
    cudaGetSymbolAddress((void**)&p_w1h  , g_w1h  );
    cudaGetSymbolAddress((void**)&p_w2h  , g_w2h  );

    const int attn_smem = (2*64*HSA + 64*HSV)*sizeof(__half);   // 27136 B
    cudaFuncSetAttribute(attn_h_kernel, cudaFuncAttributeMaxDynamicSharedMemorySize, attn_smem);
    const int gemm_smem = NSTG*(TM + TN)*HSTR*sizeof(__half);   // 92160 B
    cudaFuncSetAttribute(hgemm_kernel<0>, cudaFuncAttributeMaxDynamicSharedMemorySize, gemm_smem);
    cudaFuncSetAttribute(hgemm_kernel<1>, cudaFuncAttributeMaxDynamicSharedMemorySize, gemm_smem);
    cudaFuncSetAttribute(hgemm_kernel<2>, cudaFuncAttributeMaxDynamicSharedMemorySize, gemm_smem);

    // weight prep
    wtrans_h_kernel<<<dim3(3*DD/32, DD/32),256>>>(wqkv, p_wqkvh, DD, 3*DD);
    wtrans_h_kernel<<<dim3(DD/32,   DD/32),256>>>(wout, p_wouth, DD, DD);
    wtrans_h_kernel<<<dim3(2*DD/32, DD/32),256>>>(w1,   p_w1h,   DD, 2*DD);
    wtrans_h_kernel<<<dim3(DD/32, 2*DD/32),256>>>(w2,   p_w2h,   2*DD, DD);

    // LN1 -> fp16
    ln_kernel<<<MM,256>>>(x, ln1s, ln1b, p_xn);
    // QKV (fp16 mma) -> fp16
    hgemm_kernel<0><<<dim3(3*DD/TN, MM/TM),256,gemm_smem>>>(p_xn, p_wqkvh, nullptr, p_qkv,
                                                            MM, 3*DD, DD, nullptr, nullptr);
    // causal attention (fp16) -> fp16
    attn_h_kernel<<<dim3(NSEQ/64, BB*NH),128,attn_smem>>>(p_qkv, p_oh);
    // out-proj + residual (fp16 mma) -> fp32
    hgemm_kernel<1><<<dim3(DD/TN, MM/TM),256,gemm_smem>>>(p_oh, p_wouth, p_x1, nullptr,
                                                          MM, DD, DD, bout, x);
    // LN2 -> fp16
    ln_kernel<<<MM,256>>>(p_x1, ln2s, ln2b, p_xn2);
    // MLP up + GELU -> fp16
    hgemm_kernel<2><<<dim3(2*DD/TN, MM/TM),256,gemm_smem>>>(p_xn2, p_w1h, nullptr, p_y,
                                                            MM, 2*DD, DD, b1, nullptr);
    // MLP down + residual -> out fp32
    hgemm_kernel<1><<<dim3(DD/TN, MM/TM),256,gemm_smem>>>(p_y, p_w2h, out, nullptr,
                                                          MM, DD, 2*DD, b2, p_x1);
}